// round 8
// baseline (speedup 1.0000x reference)
#include <cuda_runtime.h>
#include <cstdint>

// Problem constants
constexpr int NE   = 1024;
constexpr int NH   = 16;
constexpr int DK   = 64;
constexpr int BB   = 2;
constexpr int TT   = 2048;
constexpr int MTOT = BB * TT;   // 4096

// Scratch (tf32 bits stored as uint32)
__device__ uint32_t g_xt[MTOT * NE];
__device__ uint32_t g_wqkv[3 * NE * NE];
__device__ uint32_t g_wo[NE * NE];
__device__ uint32_t g_q[BB * NH * TT * DK];
__device__ uint32_t g_k[BB * NH * TT * DK];
__device__ uint32_t g_v[BB * NH * TT * DK];
__device__ uint32_t g_yt[MTOT * NE];

// ---------------------------------------------------------------------------
// helpers
// ---------------------------------------------------------------------------
__device__ __forceinline__ uint32_t f2tf(float f) {
    uint32_t u;
    asm("cvt.rna.tf32.f32 %0, %1;" : "=r"(u) : "f"(f));
    return u;
}
__device__ __forceinline__ float ex2(float x) {
    float r;
    asm("ex2.approx.f32 %0, %1;" : "=f"(r) : "f"(x));
    return r;
}
__device__ __forceinline__ void mma_tf32(float c[4], const uint32_t a[4], const uint32_t b[2]) {
    asm volatile(
        "mma.sync.aligned.m16n8k8.row.col.f32.tf32.tf32.f32 "
        "{%0,%1,%2,%3}, {%4,%5,%6,%7}, {%8,%9}, {%0,%1,%2,%3};\n"
        : "+f"(c[0]), "+f"(c[1]), "+f"(c[2]), "+f"(c[3])
        : "r"(a[0]), "r"(a[1]), "r"(a[2]), "r"(a[3]), "r"(b[0]), "r"(b[1]));
}
__device__ __forceinline__ void cpa16(uint32_t dst, const void* src) {
    asm volatile("cp.async.cg.shared.global [%0], [%1], 16;" :: "r"(dst), "l"(src));
}
__device__ __forceinline__ void cpcommit() {
    asm volatile("cp.async.commit_group;");
}
template <int N>
__device__ __forceinline__ void cpwait() {
    asm volatile("cp.async.wait_group %0;" :: "n"(N));
}

// ---------------------------------------------------------------------------
// fp32 -> tf32 bulk converter (vectorized)
// ---------------------------------------------------------------------------
__global__ void cvt_tf32(const float4* __restrict__ in, uint4* __restrict__ out, int n4)
{
    int i = blockIdx.x * blockDim.x + threadIdx.x;
    if (i < n4) {
        float4 v = in[i];
        uint4 u;
        u.x = f2tf(v.x); u.y = f2tf(v.y); u.z = f2tf(v.z); u.w = f2tf(v.w);
        out[i] = u;
    }
}

// ---------------------------------------------------------------------------
// tf32 GEMM: out[m,n] = sum_k X[m,k]*W[n,k] + bias[n]
// Block 128x256, BK=16, 3-stage cp.async pipeline, 256 threads = 8 warps
// (2m x 4n), warp tile 64x64. Inputs pre-converted tf32.
// SPLIT=true: grid.z selects Wq/Wk/Wv; output tf32 bits head-major [b,h,t,d].
// SPLIT=false: fp32 output row-major.
// ---------------------------------------------------------------------------
template <bool SPLIT>
__global__ __launch_bounds__(256, 1)
void gemm_tc(const uint32_t* __restrict__ X, const uint32_t* __restrict__ Wbase,
             const float* __restrict__ bias0, const float* __restrict__ bias1,
             const float* __restrict__ bias2,
             uint32_t* __restrict__ o0, uint32_t* __restrict__ o1,
             uint32_t* __restrict__ o2, float* __restrict__ ofp)
{
    __shared__ uint32_t Xs[3][128 * 20];
    __shared__ uint32_t Ws[3][256 * 20];

    const int z = SPLIT ? blockIdx.z : 0;
    const uint32_t* W = Wbase + z * NE * NE;
    const float* bias = (z == 0) ? bias0 : (z == 1 ? bias1 : bias2);
    uint32_t* outu = (z == 0) ? o0 : (z == 1 ? o1 : o2);

    const int bn   = blockIdx.x * 256;
    const int bm   = blockIdx.y * 128;
    const int tid  = threadIdx.x;
    const int lane = tid & 31;
    const int wid  = tid >> 5;
    const int wm   = wid >> 2;      // 0..1
    const int wn   = wid & 3;       // 0..3
    const int ls   = lane >> 2;
    const int lc   = lane & 3;

    // chunk geometry for cp.async stage loads
    const int xr = tid >> 2;              // 0..63 -> X rows tid>>2 (two passes)
    const int cc = (tid & 3) * 4;         // word offset in row

    uint32_t xs_base = (uint32_t)__cvta_generic_to_shared(&Xs[0][0]);
    uint32_t ws_base = (uint32_t)__cvta_generic_to_shared(&Ws[0][0]);

    auto load_stage = [&](int buf, int k0) {
        uint32_t xb = xs_base + buf * (128 * 20 * 4);
        uint32_t wb = ws_base + buf * (256 * 20 * 4);
        #pragma unroll
        for (int i = 0; i < 2; i++) {
            int r = xr + i * 64;
            cpa16(xb + (r * 20 + cc) * 4, &X[(bm + r) * NE + k0 + cc]);
        }
        #pragma unroll
        for (int i = 0; i < 4; i++) {
            int r = xr + i * 64;
            cpa16(wb + (r * 20 + cc) * 4, &W[(bn + r) * NE + k0 + cc]);
        }
    };

    float acc[4][8][4] = {};

    auto mma_stage = [&](int buf) {
        #pragma unroll
        for (int kk = 0; kk < 16; kk += 8) {
            uint32_t a[4][4], bfr[8][2];
            #pragma unroll
            for (int i = 0; i < 4; i++) {
                int r = wm * 64 + i * 16 + ls;
                const uint32_t* p = &Xs[buf][r * 20 + kk + lc];
                a[i][0] = p[0];
                a[i][1] = p[8 * 20];
                a[i][2] = p[4];
                a[i][3] = p[8 * 20 + 4];
            }
            #pragma unroll
            for (int j = 0; j < 8; j++) {
                int c = wn * 64 + j * 8 + ls;
                const uint32_t* p = &Ws[buf][c * 20 + kk + lc];
                bfr[j][0] = p[0];
                bfr[j][1] = p[4];
            }
            #pragma unroll
            for (int i = 0; i < 4; i++)
                #pragma unroll
                for (int j = 0; j < 8; j++)
                    mma_tf32(acc[i][j], a[i], bfr[j]);
        }
    };

    constexpr int NS = NE / 16;   // 64 stages
    load_stage(0, 0);  cpcommit();
    load_stage(1, 16); cpcommit();

    for (int k = 0; k < NS; k++) {
        __syncthreads();
        if (k + 2 < NS) load_stage((k + 2) % 3, (k + 2) * 16);
        cpcommit();
        cpwait<2>();
        __syncthreads();
        mma_stage(k % 3);
    }

    // Epilogue
    #pragma unroll
    for (int i = 0; i < 4; i++) {
        const int m = bm + wm * 64 + i * 16 + ls;
        #pragma unroll
        for (int j = 0; j < 8; j++) {
            const int n = bn + wn * 64 + j * 8 + lc * 2;
            const float b0v = bias[n], b1v = bias[n + 1];
            float v00 = acc[i][j][0] + b0v, v01 = acc[i][j][1] + b1v;
            float v10 = acc[i][j][2] + b0v, v11 = acc[i][j][3] + b1v;
            if (SPLIT) {
                const int b  = m >> 11;
                const int t  = m & (TT - 1);
                const int h  = n >> 6;
                const int d  = n & 63;
                uint32_t* p0 = &outu[(((b * NH + h) * TT + t)     << 6) + d];
                uint32_t* p1 = &outu[(((b * NH + h) * TT + t + 8) << 6) + d];
                p0[0] = f2tf(v00); p0[1] = f2tf(v01);
                p1[0] = f2tf(v10); p1[1] = f2tf(v11);
            } else {
                *(float2*)&ofp[m * NE + n]       = make_float2(v00, v01);
                *(float2*)&ofp[(m + 8) * NE + n] = make_float2(v10, v11);
            }
        }
    }
}

// ---------------------------------------------------------------------------
// Tensor-core flash attention, tf32 I/O, cp.async double-buffered K/V tiles.
// Grid (16, NH, BB) with longest-first scheduling; 8 warps x 16 q-rows.
// ---------------------------------------------------------------------------
__global__ __launch_bounds__(256, 1)
void attn_tc(const uint32_t* __restrict__ Q, const uint32_t* __restrict__ K,
             const uint32_t* __restrict__ V, uint32_t* __restrict__ Y)
{
    __shared__ uint32_t Ks[2][64 * 68];
    __shared__ uint32_t Vs[2][64 * 72];

    const int qt   = gridDim.x - 1 - blockIdx.x;   // longest blocks first
    const int h    = blockIdx.y;
    const int b    = blockIdx.z;
    const int bm   = qt * 128;
    const int tid  = threadIdx.x;
    const int lane = tid & 31;
    const int w    = tid >> 5;
    const int ls   = lane >> 2;
    const int lc   = lane & 3;
    const int base = (b * NH + h) * TT;
    const int wrow = bm + w * 16;

    // Q fragments: raw tf32 bits (scale applied to S after MMA)
    uint32_t aq[8][4];
    {
        const uint32_t* q0 = Q + (base + wrow + ls) * DK;
        const uint32_t* q1 = q0 + 8 * DK;
        #pragma unroll
        for (int kk = 0; kk < 8; kk++) {
            aq[kk][0] = q0[kk * 8 + lc];
            aq[kk][1] = q1[kk * 8 + lc];
            aq[kk][2] = q0[kk * 8 + 4 + lc];
            aq[kk][3] = q1[kk * 8 + 4 + lc];
        }
    }

    float o[8][4] = {};
    float m0 = -1e30f, m1 = -1e30f;
    float l0 = 0.f,    l1 = 0.f;

    const int ldrow = tid >> 2;
    const int ldcol = (tid & 3) * 16;

    uint32_t ks_base = (uint32_t)__cvta_generic_to_shared(&Ks[0][0]);
    uint32_t vs_base = (uint32_t)__cvta_generic_to_shared(&Vs[0][0]);

    auto load_tile = [&](int buf, int kb) {
        const uint32_t* kp = K + (base + kb * 64 + ldrow) * DK + ldcol;
        const uint32_t* vp = V + (base + kb * 64 + ldrow) * DK + ldcol;
        uint32_t kd = ks_base + buf * (64 * 68 * 4) + (ldrow * 68 + ldcol) * 4;
        uint32_t vd = vs_base + buf * (64 * 72 * 4) + (ldrow * 72 + ldcol) * 4;
        #pragma unroll
        for (int i = 0; i < 4; i++) {
            cpa16(kd + i * 16, kp + i * 4);
            cpa16(vd + i * 16, vp + i * 4);
        }
    };

    const int nkb = 2 * qt + 2;
    load_tile(0, 0);
    cpcommit();

    const float SC = 0.125f * 1.44269504f;   // 1/sqrt(64) * log2(e)

    for (int kb = 0; kb < nkb; kb++) {
        const int buf = kb & 1;
        __syncthreads();                       // prev compute done -> buf^1 free
        if (kb + 1 < nkb) load_tile(buf ^ 1, kb + 1);
        cpcommit();
        cpwait<1>();
        __syncthreads();

        if (kb * 64 <= wrow + 15) {
            // ---- S = Q K^T ----
            float s[8][4];
            #pragma unroll
            for (int j = 0; j < 8; j++)
                s[j][0] = s[j][1] = s[j][2] = s[j][3] = 0.f;

            #pragma unroll
            for (int kk = 0; kk < 8; kk++) {
                #pragma unroll
                for (int j = 0; j < 8; j++) {
                    uint32_t bb[2];
                    bb[0] = Ks[buf][(j * 8 + ls) * 68 + kk * 8 + lc];
                    bb[1] = Ks[buf][(j * 8 + ls) * 68 + kk * 8 + 4 + lc];
                    mma_tf32(s[j], aq[kk], bb);
                }
            }

            const int row0 = wrow + ls;
            const int row1 = row0 + 8;

            // scale
            #pragma unroll
            for (int j = 0; j < 8; j++) {
                s[j][0] *= SC; s[j][1] *= SC; s[j][2] *= SC; s[j][3] *= SC;
            }

            // causal mask (diagonal tiles only)
            if (kb * 64 + 63 > row0) {
                #pragma unroll
                for (int j = 0; j < 8; j++) {
                    const int col = kb * 64 + j * 8 + lc * 2;
                    if (col     > row0) s[j][0] = -1e30f;
                    if (col + 1 > row0) s[j][1] = -1e30f;
                    if (col     > row1) s[j][2] = -1e30f;
                    if (col + 1 > row1) s[j][3] = -1e30f;
                }
            }

            // online softmax
            float mx0 = -1e30f, mx1 = -1e30f;
            #pragma unroll
            for (int j = 0; j < 8; j++) {
                mx0 = fmaxf(mx0, fmaxf(s[j][0], s[j][1]));
                mx1 = fmaxf(mx1, fmaxf(s[j][2], s[j][3]));
            }
            mx0 = fmaxf(mx0, __shfl_xor_sync(0xffffffffu, mx0, 1));
            mx0 = fmaxf(mx0, __shfl_xor_sync(0xffffffffu, mx0, 2));
            mx1 = fmaxf(mx1, __shfl_xor_sync(0xffffffffu, mx1, 1));
            mx1 = fmaxf(mx1, __shfl_xor_sync(0xffffffffu, mx1, 2));

            const float mn0 = fmaxf(m0, mx0);
            const float mn1 = fmaxf(m1, mx1);
            const float cr0 = ex2(m0 - mn0);
            const float cr1 = ex2(m1 - mn1);
            m0 = mn0; m1 = mn1;
            l0 *= cr0; l1 *= cr1;

            float ps0 = 0.f, ps1 = 0.f;
            #pragma unroll
            for (int j = 0; j < 8; j++) {
                o[j][0] *= cr0; o[j][1] *= cr0;
                o[j][2] *= cr1; o[j][3] *= cr1;
                float p0 = ex2(s[j][0] - mn0);
                float p1 = ex2(s[j][1] - mn0);
                float p2 = ex2(s[j][2] - mn1);
                float p3 = ex2(s[j][3] - mn1);
                ps0 += p0 + p1;
                ps1 += p2 + p3;
                s[j][0] = __uint_as_float(f2tf(p0));
                s[j][1] = __uint_as_float(f2tf(p1));
                s[j][2] = __uint_as_float(f2tf(p2));
                s[j][3] = __uint_as_float(f2tf(p3));
            }
            l0 += ps0; l1 += ps1;

            // ---- O += P V ----
            const int srcA = (lane & ~3) | (lc >> 1);
            const int srcB = srcA + 2;
            const bool odd = lane & 1;
            #pragma unroll
            for (int kk = 0; kk < 8; kk++) {
                float v00 = __shfl_sync(0xffffffffu, s[kk][0], srcA);
                float v01 = __shfl_sync(0xffffffffu, s[kk][1], srcA);
                float v10 = __shfl_sync(0xffffffffu, s[kk][2], srcA);
                float v11 = __shfl_sync(0xffffffffu, s[kk][3], srcA);
                float w00 = __shfl_sync(0xffffffffu, s[kk][0], srcB);
                float w01 = __shfl_sync(0xffffffffu, s[kk][1], srcB);
                float w10 = __shfl_sync(0xffffffffu, s[kk][2], srcB);
                float w11 = __shfl_sync(0xffffffffu, s[kk][3], srcB);
                uint32_t a[4];
                a[0] = __float_as_uint(odd ? v01 : v00);
                a[1] = __float_as_uint(odd ? v11 : v10);
                a[2] = __float_as_uint(odd ? w01 : w00);
                a[3] = __float_as_uint(odd ? w11 : w10);
                #pragma unroll
                for (int j = 0; j < 8; j++) {
                    uint32_t bb[2];
                    bb[0] = Vs[buf][(kk * 8 + lc) * 72 + j * 8 + ls];
                    bb[1] = Vs[buf][(kk * 8 + 4 + lc) * 72 + j * 8 + ls];
                    mma_tf32(o[j], a, bb);
                }
            }
        }
    }

    // reduce l, normalize, store y as tf32 bits
    l0 += __shfl_xor_sync(0xffffffffu, l0, 1);
    l0 += __shfl_xor_sync(0xffffffffu, l0, 2);
    l1 += __shfl_xor_sync(0xffffffffu, l1, 1);
    l1 += __shfl_xor_sync(0xffffffffu, l1, 2);
    const float i0 = 1.f / l0;
    const float i1 = 1.f / l1;

    const int row0 = wrow + ls;
    uint32_t* y0 = Y + (b * TT + row0)     * NE + h * DK;
    uint32_t* y1 = Y + (b * TT + row0 + 8) * NE + h * DK;
    #pragma unroll
    for (int j = 0; j < 8; j++) {
        y0[j * 8 + lc * 2]     = f2tf(o[j][0] * i0);
        y0[j * 8 + lc * 2 + 1] = f2tf(o[j][1] * i0);
        y1[j * 8 + lc * 2]     = f2tf(o[j][2] * i1);
        y1[j * 8 + lc * 2 + 1] = f2tf(o[j][3] * i1);
    }
}

// ---------------------------------------------------------------------------
extern "C" void kernel_launch(void* const* d_in, const int* in_sizes, int n_in,
                              void* d_out, int out_size)
{
    const float* x  = (const float*)d_in[0];
    const float* Wq = (const float*)d_in[1];
    const float* bq = (const float*)d_in[2];
    const float* Wk = (const float*)d_in[3];
    const float* bk = (const float*)d_in[4];
    const float* Wv = (const float*)d_in[5];
    const float* bv = (const float*)d_in[6];
    const float* Wo = (const float*)d_in[7];
    const float* bo = (const float*)d_in[8];
    float* out = (float*)d_out;

    uint32_t *xt, *wqkv, *wo, *q, *k, *v, *yt;
    cudaGetSymbolAddress((void**)&xt,   g_xt);
    cudaGetSymbolAddress((void**)&wqkv, g_wqkv);
    cudaGetSymbolAddress((void**)&wo,   g_wo);
    cudaGetSymbolAddress((void**)&q,    g_q);
    cudaGetSymbolAddress((void**)&k,    g_k);
    cudaGetSymbolAddress((void**)&v,    g_v);
    cudaGetSymbolAddress((void**)&yt,   g_yt);

    // pre-convert inputs to tf32
    const int n4x = MTOT * NE / 4;       // 1,048,576
    const int n4w = NE * NE / 4;         // 262,144
    cvt_tf32<<<(n4x + 255) / 256, 256>>>((const float4*)x,  (uint4*)xt,   n4x);
    cvt_tf32<<<(n4w + 255) / 256, 256>>>((const float4*)Wq, (uint4*)wqkv, n4w);
    cvt_tf32<<<(n4w + 255) / 256, 256>>>((const float4*)Wk, (uint4*)(wqkv + NE * NE), n4w);
    cvt_tf32<<<(n4w + 255) / 256, 256>>>((const float4*)Wv, (uint4*)(wqkv + 2 * NE * NE), n4w);
    cvt_tf32<<<(n4w + 255) / 256, 256>>>((const float4*)Wo, (uint4*)wo,   n4w);

    // fused QKV projection (grid.z selects matrix)
    gemm_tc<true><<<dim3(NE / 256, MTOT / 128, 3), 256>>>(
        xt, wqkv, bq, bk, bv, q, k, v, nullptr);

    // attention
    attn_tc<<<dim3(TT / 128, NH, BB), 256>>>(q, k, v, yt);

    // output projection
    gemm_tc<false><<<dim3(NE / 256, MTOT / 128, 1), 256>>>(
        yt, wo, bo, nullptr, nullptr, nullptr, nullptr, nullptr, out);
}

// round 9
// speedup vs baseline: 1.4563x; 1.4563x over previous
#include <cuda_runtime.h>
#include <cstdint>

// Problem constants
constexpr int NE   = 1024;
constexpr int NH   = 16;
constexpr int DK   = 64;
constexpr int BB   = 2;
constexpr int TT   = 2048;
constexpr int MTOT = BB * TT;   // 4096

// Scratch (tf32 bits stored as uint32)
__device__ uint32_t g_xt[MTOT * NE];
__device__ uint32_t g_wqkv[3 * NE * NE];
__device__ uint32_t g_wo[NE * NE];
__device__ uint32_t g_q[BB * NH * TT * DK];
__device__ uint32_t g_k[BB * NH * TT * DK];
__device__ uint32_t g_v[BB * NH * TT * DK];
__device__ uint32_t g_yt[MTOT * NE];

// ---------------------------------------------------------------------------
// helpers
// ---------------------------------------------------------------------------
__device__ __forceinline__ uint32_t f2tf(float f) {
    uint32_t u;
    asm("cvt.rna.tf32.f32 %0, %1;" : "=r"(u) : "f"(f));
    return u;
}
__device__ __forceinline__ float ex2(float x) {
    float r;
    asm("ex2.approx.f32 %0, %1;" : "=f"(r) : "f"(x));
    return r;
}
__device__ __forceinline__ void mma_tf32(float c[4], const uint32_t a[4], const uint32_t b[2]) {
    asm volatile(
        "mma.sync.aligned.m16n8k8.row.col.f32.tf32.tf32.f32 "
        "{%0,%1,%2,%3}, {%4,%5,%6,%7}, {%8,%9}, {%0,%1,%2,%3};\n"
        : "+f"(c[0]), "+f"(c[1]), "+f"(c[2]), "+f"(c[3])
        : "r"(a[0]), "r"(a[1]), "r"(a[2]), "r"(a[3]), "r"(b[0]), "r"(b[1]));
}

// ---------------------------------------------------------------------------
// fp32 -> tf32 bulk converter
// ---------------------------------------------------------------------------
__global__ void cvt_tf32(const float4* __restrict__ in, uint4* __restrict__ out, int n4)
{
    int i = blockIdx.x * blockDim.x + threadIdx.x;
    if (i < n4) {
        float4 v = in[i];
        uint4 u;
        u.x = f2tf(v.x); u.y = f2tf(v.y); u.z = f2tf(v.z); u.w = f2tf(v.w);
        out[i] = u;
    }
}

// ---------------------------------------------------------------------------
// tf32 GEMM (structure of the 571us version): out[m,n] = X[m,:]*W[n,:] + bias
// Block 128x128, BK=16, double-buffered LDG->STS, 8 warps (2m x 4n), 64x32.
// Inputs are pre-converted tf32 bits -> no cvt in the mainloop.
// SPLIT=true: grid.z selects Wq/Wk/Wv, writes tf32 bits head-major [b,h,t,d].
// SPLIT=false: writes fp32 row-major.
// ---------------------------------------------------------------------------
template <bool SPLIT>
__global__ __launch_bounds__(256, 2)
void gemm_tc(const uint32_t* __restrict__ X, const uint32_t* __restrict__ Wbase,
             const float* __restrict__ bias0, const float* __restrict__ bias1,
             const float* __restrict__ bias2,
             uint32_t* __restrict__ o0, uint32_t* __restrict__ o1,
             uint32_t* __restrict__ o2, float* __restrict__ ofp)
{
    __shared__ uint32_t Xs[2][128 * 20];
    __shared__ uint32_t Ws[2][128 * 20];

    const int z = SPLIT ? blockIdx.z : 0;
    const uint32_t* W = Wbase + z * NE * NE;
    const float* bias = (z == 0) ? bias0 : (z == 1 ? bias1 : bias2);
    uint32_t* outu = (z == 0) ? o0 : (z == 1 ? o1 : o2);

    const int bn   = blockIdx.x * 128;
    const int bm   = blockIdx.y * 128;
    const int tid  = threadIdx.x;
    const int lane = tid & 31;
    const int wid  = tid >> 5;
    const int wm   = wid >> 2;
    const int wn   = wid & 3;

    const int r0 = tid >> 2;
    const int c0 = (tid & 3) * 4;

    uint4 xa, xb, wa, wb;

    auto LOAD = [&](int k0) {
        xa = *(const uint4*)&X[(bm + r0)      * NE + k0 + c0];
        xb = *(const uint4*)&X[(bm + r0 + 64) * NE + k0 + c0];
        wa = *(const uint4*)&W[(bn + r0)      * NE + k0 + c0];
        wb = *(const uint4*)&W[(bn + r0 + 64) * NE + k0 + c0];
    };

    auto STS = [&](int buf) {
        *(uint4*)&Xs[buf][r0 * 20 + c0]        = xa;
        *(uint4*)&Xs[buf][(r0 + 64) * 20 + c0] = xb;
        *(uint4*)&Ws[buf][r0 * 20 + c0]        = wa;
        *(uint4*)&Ws[buf][(r0 + 64) * 20 + c0] = wb;
    };

    float acc[4][4][4] = {};

    auto MMA_STAGE = [&](int buf) {
        #pragma unroll
        for (int kk = 0; kk < 16; kk += 8) {
            uint32_t a[4][4], b[4][2];
            #pragma unroll
            for (int i = 0; i < 4; i++) {
                int r = wm * 64 + i * 16 + (lane >> 2);
                const uint32_t* p = &Xs[buf][r * 20 + kk + (lane & 3)];
                a[i][0] = p[0];
                a[i][1] = p[8 * 20];
                a[i][2] = p[4];
                a[i][3] = p[8 * 20 + 4];
            }
            #pragma unroll
            for (int j = 0; j < 4; j++) {
                int c = wn * 32 + j * 8 + (lane >> 2);
                const uint32_t* p = &Ws[buf][c * 20 + kk + (lane & 3)];
                b[j][0] = p[0];
                b[j][1] = p[4];
            }
            #pragma unroll
            for (int i = 0; i < 4; i++)
                #pragma unroll
                for (int j = 0; j < 4; j++)
                    mma_tf32(acc[i][j], a[i], b[j]);
        }
    };

    LOAD(0);
    STS(0);
    __syncthreads();

    int cur = 0;
    for (int k0 = 16; k0 < NE; k0 += 16) {
        LOAD(k0);
        MMA_STAGE(cur);
        STS(cur ^ 1);
        __syncthreads();
        cur ^= 1;
    }
    MMA_STAGE(cur);

    #pragma unroll
    for (int i = 0; i < 4; i++) {
        const int m = bm + wm * 64 + i * 16 + (lane >> 2);
        #pragma unroll
        for (int j = 0; j < 4; j++) {
            const int n = bn + wn * 32 + j * 8 + (lane & 3) * 2;
            const float b0v = bias[n], b1v = bias[n + 1];
            float v00 = acc[i][j][0] + b0v, v01 = acc[i][j][1] + b1v;
            float v10 = acc[i][j][2] + b0v, v11 = acc[i][j][3] + b1v;
            if (SPLIT) {
                const int b  = m >> 11;
                const int t  = m & (TT - 1);
                const int h  = n >> 6;
                const int d  = n & 63;
                uint2 u0 = make_uint2(f2tf(v00), f2tf(v01));
                uint2 u1 = make_uint2(f2tf(v10), f2tf(v11));
                *(uint2*)&outu[(((b * NH + h) * TT + t)     << 6) + d] = u0;
                *(uint2*)&outu[(((b * NH + h) * TT + t + 8) << 6) + d] = u1;
            } else {
                *(float2*)&ofp[m * NE + n]       = make_float2(v00, v01);
                *(float2*)&ofp[(m + 8) * NE + n] = make_float2(v10, v11);
            }
        }
    }
}

// ---------------------------------------------------------------------------
// Tensor-core flash attention (structure of the 245us version), tf32 I/O.
// Grid (16, NH, BB) longest-first; 8 warps x 16 q-rows; register-prefetched
// single-buffer K/V tiles (raw tf32 stores, no cvt).
// ---------------------------------------------------------------------------
__global__ __launch_bounds__(256)
void attn_tc(const uint32_t* __restrict__ Q, const uint32_t* __restrict__ K,
             const uint32_t* __restrict__ V, uint32_t* __restrict__ Y)
{
    __shared__ uint32_t Ks[64 * 68];
    __shared__ uint32_t Vs[64 * 72];

    const int qt   = gridDim.x - 1 - blockIdx.x;   // longest blocks first
    const int h    = blockIdx.y;
    const int b    = blockIdx.z;
    const int bm   = qt * 128;
    const int tid  = threadIdx.x;
    const int lane = tid & 31;
    const int w    = tid >> 5;
    const int ls   = lane >> 2;
    const int lc   = lane & 3;
    const int base = (b * NH + h) * TT;
    const int wrow = bm + w * 16;

    // Q fragments: raw tf32 bits (softmax scale applied to S post-MMA)
    uint32_t aq[8][4];
    {
        const uint32_t* q0 = Q + (base + wrow + ls) * DK;
        const uint32_t* q1 = q0 + 8 * DK;
        #pragma unroll
        for (int kk = 0; kk < 8; kk++) {
            aq[kk][0] = q0[kk * 8 + lc];
            aq[kk][1] = q1[kk * 8 + lc];
            aq[kk][2] = q0[kk * 8 + 4 + lc];
            aq[kk][3] = q1[kk * 8 + 4 + lc];
        }
    }

    float o[8][4] = {};
    float m0 = -1e30f, m1 = -1e30f;
    float l0 = 0.f,    l1 = 0.f;

    const int ldrow = tid >> 2;
    const int ldcol = (tid & 3) * 16;

    const int nkb = 2 * qt + 2;

    uint4 kreg[4], vreg[4];
    {
        const uint4* kp = (const uint4*)&K[(base + ldrow) * DK + ldcol];
        const uint4* vp = (const uint4*)&V[(base + ldrow) * DK + ldcol];
        #pragma unroll
        for (int i = 0; i < 4; i++) { kreg[i] = kp[i]; vreg[i] = vp[i]; }
    }

    const float SC = 0.125f * 1.44269504f;   // 1/sqrt(64) * log2(e)

    for (int kb = 0; kb < nkb; kb++) {
        __syncthreads();
        #pragma unroll
        for (int i = 0; i < 4; i++) {
            *(uint4*)&Ks[ldrow * 68 + ldcol + i * 4] = kreg[i];
            *(uint4*)&Vs[ldrow * 72 + ldcol + i * 4] = vreg[i];
        }
        __syncthreads();

        if (kb + 1 < nkb) {
            const uint4* kp = (const uint4*)&K[(base + (kb + 1) * 64 + ldrow) * DK + ldcol];
            const uint4* vp = (const uint4*)&V[(base + (kb + 1) * 64 + ldrow) * DK + ldcol];
            #pragma unroll
            for (int i = 0; i < 4; i++) { kreg[i] = kp[i]; vreg[i] = vp[i]; }
        }

        if (kb * 64 > wrow + 15) continue;   // whole warp slab masked

        // ---- S = Q K^T ----
        float s[8][4];
        #pragma unroll
        for (int j = 0; j < 8; j++)
            s[j][0] = s[j][1] = s[j][2] = s[j][3] = 0.f;

        #pragma unroll
        for (int kk = 0; kk < 8; kk++) {
            #pragma unroll
            for (int j = 0; j < 8; j++) {
                uint32_t bb[2];
                bb[0] = Ks[(j * 8 + ls) * 68 + kk * 8 + lc];
                bb[1] = Ks[(j * 8 + ls) * 68 + kk * 8 + 4 + lc];
                mma_tf32(s[j], aq[kk], bb);
            }
        }

        const int row0 = wrow + ls;
        const int row1 = row0 + 8;

        // scale
        #pragma unroll
        for (int j = 0; j < 8; j++) {
            s[j][0] *= SC; s[j][1] *= SC; s[j][2] *= SC; s[j][3] *= SC;
        }

        // causal mask (diagonal tiles only)
        if (kb * 64 + 63 > row0) {
            #pragma unroll
            for (int j = 0; j < 8; j++) {
                const int col = kb * 64 + j * 8 + lc * 2;
                if (col     > row0) s[j][0] = -1e30f;
                if (col + 1 > row0) s[j][1] = -1e30f;
                if (col     > row1) s[j][2] = -1e30f;
                if (col + 1 > row1) s[j][3] = -1e30f;
            }
        }

        // ---- online softmax ----
        float mx0 = -1e30f, mx1 = -1e30f;
        #pragma unroll
        for (int j = 0; j < 8; j++) {
            mx0 = fmaxf(mx0, fmaxf(s[j][0], s[j][1]));
            mx1 = fmaxf(mx1, fmaxf(s[j][2], s[j][3]));
        }
        mx0 = fmaxf(mx0, __shfl_xor_sync(0xffffffffu, mx0, 1));
        mx0 = fmaxf(mx0, __shfl_xor_sync(0xffffffffu, mx0, 2));
        mx1 = fmaxf(mx1, __shfl_xor_sync(0xffffffffu, mx1, 1));
        mx1 = fmaxf(mx1, __shfl_xor_sync(0xffffffffu, mx1, 2));

        const float mn0 = fmaxf(m0, mx0);
        const float mn1 = fmaxf(m1, mx1);
        const float cr0 = ex2(m0 - mn0);
        const float cr1 = ex2(m1 - mn1);
        m0 = mn0; m1 = mn1;
        l0 *= cr0; l1 *= cr1;

        float ps0 = 0.f, ps1 = 0.f;
        #pragma unroll
        for (int j = 0; j < 8; j++) {
            o[j][0] *= cr0; o[j][1] *= cr0;
            o[j][2] *= cr1; o[j][3] *= cr1;
            float p0 = ex2(s[j][0] - mn0);
            float p1 = ex2(s[j][1] - mn0);
            float p2 = ex2(s[j][2] - mn1);
            float p3 = ex2(s[j][3] - mn1);
            ps0 += p0 + p1;
            ps1 += p2 + p3;
            s[j][0] = __uint_as_float(f2tf(p0));
            s[j][1] = __uint_as_float(f2tf(p1));
            s[j][2] = __uint_as_float(f2tf(p2));
            s[j][3] = __uint_as_float(f2tf(p3));
        }
        l0 += ps0; l1 += ps1;

        // ---- O += P V ----
        const int srcA = (lane & ~3) | (lc >> 1);
        const int srcB = srcA + 2;
        const bool odd = lane & 1;
        #pragma unroll
        for (int kk = 0; kk < 8; kk++) {
            float v00 = __shfl_sync(0xffffffffu, s[kk][0], srcA);
            float v01 = __shfl_sync(0xffffffffu, s[kk][1], srcA);
            float v10 = __shfl_sync(0xffffffffu, s[kk][2], srcA);
            float v11 = __shfl_sync(0xffffffffu, s[kk][3], srcA);
            float w00 = __shfl_sync(0xffffffffu, s[kk][0], srcB);
            float w01 = __shfl_sync(0xffffffffu, s[kk][1], srcB);
            float w10 = __shfl_sync(0xffffffffu, s[kk][2], srcB);
            float w11 = __shfl_sync(0xffffffffu, s[kk][3], srcB);
            uint32_t a[4];
            a[0] = __float_as_uint(odd ? v01 : v00);
            a[1] = __float_as_uint(odd ? v11 : v10);
            a[2] = __float_as_uint(odd ? w01 : w00);
            a[3] = __float_as_uint(odd ? w11 : w10);
            #pragma unroll
            for (int j = 0; j < 8; j++) {
                uint32_t bb[2];
                bb[0] = Vs[(kk * 8 + lc) * 72 + j * 8 + ls];
                bb[1] = Vs[(kk * 8 + 4 + lc) * 72 + j * 8 + ls];
                mma_tf32(o[j], a, bb);
            }
        }
    }

    // reduce l, normalize, store y as tf32 bits
    l0 += __shfl_xor_sync(0xffffffffu, l0, 1);
    l0 += __shfl_xor_sync(0xffffffffu, l0, 2);
    l1 += __shfl_xor_sync(0xffffffffu, l1, 1);
    l1 += __shfl_xor_sync(0xffffffffu, l1, 2);
    const float i0 = 1.f / l0;
    const float i1 = 1.f / l1;

    const int row0 = wrow + ls;
    uint32_t* y0 = Y + (b * TT + row0)     * NE + h * DK;
    uint32_t* y1 = Y + (b * TT + row0 + 8) * NE + h * DK;
    #pragma unroll
    for (int j = 0; j < 8; j++) {
        *(uint2*)&y0[j * 8 + lc * 2] = make_uint2(f2tf(o[j][0] * i0), f2tf(o[j][1] * i0));
        *(uint2*)&y1[j * 8 + lc * 2] = make_uint2(f2tf(o[j][2] * i1), f2tf(o[j][3] * i1));
    }
}

// ---------------------------------------------------------------------------
extern "C" void kernel_launch(void* const* d_in, const int* in_sizes, int n_in,
                              void* d_out, int out_size)
{
    const float* x  = (const float*)d_in[0];
    const float* Wq = (const float*)d_in[1];
    const float* bq = (const float*)d_in[2];
    const float* Wk = (const float*)d_in[3];
    const float* bk = (const float*)d_in[4];
    const float* Wv = (const float*)d_in[5];
    const float* bv = (const float*)d_in[6];
    const float* Wo = (const float*)d_in[7];
    const float* bo = (const float*)d_in[8];
    float* out = (float*)d_out;

    uint32_t *xt, *wqkv, *wo, *q, *k, *v, *yt;
    cudaGetSymbolAddress((void**)&xt,   g_xt);
    cudaGetSymbolAddress((void**)&wqkv, g_wqkv);
    cudaGetSymbolAddress((void**)&wo,   g_wo);
    cudaGetSymbolAddress((void**)&q,    g_q);
    cudaGetSymbolAddress((void**)&k,    g_k);
    cudaGetSymbolAddress((void**)&v,    g_v);
    cudaGetSymbolAddress((void**)&yt,   g_yt);

    // pre-convert inputs to tf32 (once)
    const int n4x = MTOT * NE / 4;
    const int n4w = NE * NE / 4;
    cvt_tf32<<<(n4x + 255) / 256, 256>>>((const float4*)x,  (uint4*)xt,   n4x);
    cvt_tf32<<<(n4w + 255) / 256, 256>>>((const float4*)Wq, (uint4*)wqkv, n4w);
    cvt_tf32<<<(n4w + 255) / 256, 256>>>((const float4*)Wk, (uint4*)(wqkv + NE * NE), n4w);
    cvt_tf32<<<(n4w + 255) / 256, 256>>>((const float4*)Wv, (uint4*)(wqkv + 2 * NE * NE), n4w);
    cvt_tf32<<<(n4w + 255) / 256, 256>>>((const float4*)Wo, (uint4*)wo,   n4w);

    // fused QKV projection (grid.z selects matrix), 128x128 tiles
    gemm_tc<true><<<dim3(NE / 128, MTOT / 128, 3), 256>>>(
        xt, wqkv, bq, bk, bv, q, k, v, nullptr);

    // attention
    attn_tc<<<dim3(TT / 128, NH, BB), 256>>>(q, k, v, yt);

    // output projection
    gemm_tc<false><<<dim3(NE / 128, MTOT / 128, 1), 256>>>(
        yt, wo, bo, nullptr, nullptr, nullptr, nullptr, nullptr, out);
}